// round 13
// baseline (speedup 1.0000x reference)
#include <cuda_runtime.h>
#include <cuda_bf16.h>
#include <math_constants.h>
#include <cstdint>

#define BB 64
#define SS 4096
#define DD 256
#define ROWS 16                       // rows per tile
#define TILES 8                       // tiles per CTA -> 128 rows per CTA
#define NCC (SS / (ROWS * TILES))     // 32 chunks per batch
#define PIPE 3                        // TMA pipeline depth
#define TILE_B (ROWS * DD * 4)        // 16 KB

// Scratch (allocation-free __device__ globals; zero-init at load,
// re-zeroed by ta_norm_kernel every launch for graph-replay determinism)
__device__ float g_acc[BB * DD];           // unnormalized output accumulators
__device__ float g_L[BB];                  // per-batch exp-sums

__device__ __forceinline__ uint32_t smem_u32(const void* p) {
    uint32_t a;
    asm("{ .reg .u64 t; cvta.to.shared.u64 t, %1; cvt.u32.u64 %0, t; }"
        : "=r"(a) : "l"(p));
    return a;
}

__device__ __forceinline__ void mbar_wait(uint32_t mbar, uint32_t parity) {
    asm volatile(
        "{\n\t"
        ".reg .pred P;\n\t"
        "WAIT_%=:\n\t"
        "mbarrier.try_wait.parity.acquire.cta.shared::cta.b64 P, [%0], %1, 0x989680;\n\t"
        "@P bra.uni DONE_%=;\n\t"
        "bra.uni WAIT_%=;\n\t"
        "DONE_%=:\n\t"
        "}" :: "r"(mbar), "r"(parity) : "memory");
}

__device__ __forceinline__ void tma_tile(uint32_t mb, uint32_t sdst, const float* src) {
    asm volatile("mbarrier.arrive.expect_tx.shared.b64 _, [%0], %1;"
                 :: "r"(mb), "r"((uint32_t)TILE_B) : "memory");
    asm volatile(
        "cp.async.bulk.shared::cta.global.mbarrier::complete_tx::bytes "
        "[%0], [%1], %2, [%3];"
        :: "r"(sdst), "l"(src), "r"((uint32_t)TILE_B), "r"(mb) : "memory");
}

// ---------------------------------------------------------------------------
// Kernel 1: grid = BB * NCC = 2048 CTAs, 256 threads (8 warps).
//   DEPTH-3 TMA pipeline (two tiles in flight during compute) over the proven
//   R9 mainloop: all-lane dot broadcast via xor-shuffle, register
//   accumulators, 1 barrier/tile, REDG atomics into g_acc/g_L.
// ---------------------------------------------------------------------------
__global__ __launch_bounds__(256) void ta_partial_kernel(
    const float* __restrict__ enc,   // [B, S, D]
    const float* __restrict__ Ww,    // [1, D]
    const float* __restrict__ ut)    // [1, 1]
{
    __shared__ __align__(128) float sx[PIPE][ROWS][DD];   // 3 x 16 KB
    __shared__ float sl[8];
    __shared__ __align__(8) unsigned long long mbar[PIPE];

    const int blk  = blockIdx.x;
    const int b    = blk >> 5;        // / NCC
    const int cc   = blk & (NCC - 1);
    const int tid  = threadIdx.x;
    const int w    = tid >> 5;
    const int lane = tid & 31;

    uint32_t mbs[PIPE], sds[PIPE];
    #pragma unroll
    for (int i = 0; i < PIPE; i++) {
        mbs[i] = smem_u32(&mbar[i]);
        sds[i] = smem_u32(&sx[i][0][0]);
    }

    if (tid == 0) {
        #pragma unroll
        for (int i = 0; i < PIPE; i++)
            asm volatile("mbarrier.init.shared.b64 [%0], 1;" :: "r"(mbs[i]) : "memory");
    }
    __syncthreads();

    const float* src0 = enc + ((size_t)b * SS + (size_t)cc * ROWS * TILES) * DD;

    if (tid == 0) {
        #pragma unroll
        for (int i = 0; i < PIPE; i++)
            tma_tile(mbs[i], sds[i], src0 + (size_t)i * ROWS * DD);
    }

    const float u = ut[0];
    const float4 w0 = reinterpret_cast<const float4*>(Ww)[lane];
    const float4 w1 = reinterpret_cast<const float4*>(Ww)[lane + 32];

    // 8 accumulators: cols {4*lane+0..3} and {128+4*lane+0..3}
    float4 acc0 = make_float4(0.f, 0.f, 0.f, 0.f);
    float4 acc1 = make_float4(0.f, 0.f, 0.f, 0.f);
    float lw = 0.f;   // lane-0 exp-sum

    #pragma unroll
    for (int k = 0; k < TILES; k++) {
        const int buf = k % PIPE;
        mbar_wait(mbs[buf], (k / PIPE) & 1);

        const float4* t4 = reinterpret_cast<const float4*>(&sx[buf][0][0]);
        const float4 a00 = t4[w * 64 + lane];
        const float4 a01 = t4[w * 64 + lane + 32];
        const float4 a10 = t4[(w + 8) * 64 + lane];
        const float4 a11 = t4[(w + 8) * 64 + lane + 32];

        float p0x = a00.x * w0.x, p0y = a00.y * w0.y;
        float p1x = a10.x * w0.x, p1y = a10.y * w0.y;
        p0x = fmaf(a00.z, w0.z, p0x); p0y = fmaf(a00.w, w0.w, p0y);
        p1x = fmaf(a10.z, w0.z, p1x); p1y = fmaf(a10.w, w0.w, p1y);
        p0x = fmaf(a01.x, w1.x, p0x); p0y = fmaf(a01.y, w1.y, p0y);
        p1x = fmaf(a11.x, w1.x, p1x); p1y = fmaf(a11.y, w1.y, p1y);
        p0x = fmaf(a01.z, w1.z, p0x); p0y = fmaf(a01.w, w1.w, p0y);
        p1x = fmaf(a11.z, w1.z, p1x); p1y = fmaf(a11.w, w1.w, p1y);
        float p0 = p0x + p0y;
        float p1 = p1x + p1y;
        #pragma unroll
        for (int off = 16; off > 0; off >>= 1) {
            p0 += __shfl_xor_sync(0xffffffffu, p0, off);
            p1 += __shfl_xor_sync(0xffffffffu, p1, off);
        }

        // every lane has the full dots -> local exp, no broadcast needed
        const float e0 = __expf(u * p0);
        const float e1 = __expf(u * p1);
        if (lane == 0) lw += e0 + e1;

        acc0.x = fmaf(e0, a00.x, fmaf(e1, a10.x, acc0.x));
        acc0.y = fmaf(e0, a00.y, fmaf(e1, a10.y, acc0.y));
        acc0.z = fmaf(e0, a00.z, fmaf(e1, a10.z, acc0.z));
        acc0.w = fmaf(e0, a00.w, fmaf(e1, a10.w, acc0.w));
        acc1.x = fmaf(e0, a01.x, fmaf(e1, a11.x, acc1.x));
        acc1.y = fmaf(e0, a01.y, fmaf(e1, a11.y, acc1.y));
        acc1.z = fmaf(e0, a01.z, fmaf(e1, a11.z, acc1.z));
        acc1.w = fmaf(e0, a01.w, fmaf(e1, a11.w, acc1.w));

        __syncthreads();   // all warps done with sx[buf] before refill

        if (tid == 0 && k + PIPE < TILES)
            tma_tile(mbs[buf], sds[buf], src0 + (size_t)(k + PIPE) * ROWS * DD);
    }

    // ---- cross-warp column reduce in smem (reuse buffer 0) ----
    float4* sred4 = reinterpret_cast<float4*>(&sx[0][0][0]);  // [8][64] float4
    sred4[w * 64 + lane]      = acc0;
    sred4[w * 64 + 32 + lane] = acc1;
    if (lane == 0) sl[w] = lw;
    __syncthreads();

    const float* sred = &sx[0][0][0];
    float s = 0.f;
    #pragma unroll
    for (int i = 0; i < 8; i++)
        s += sred[i * DD + tid];
    atomicAdd(&g_acc[b * DD + tid], s);   // REDG, L2-resident

    if (tid == 0) {
        float L = sl[0];
        #pragma unroll
        for (int i = 1; i < 8; i++) L += sl[i];
        atomicAdd(&g_L[b], L);
    }

    // PDL trigger (no measured harm; lets the norm launch begin early)
    cudaTriggerProgrammaticLaunchCompletion();
}

// ---------------------------------------------------------------------------
// Kernel 2 (PDL secondary): grid = BB, 256 threads.
//   Normalize + reset scratch for next graph replay.
// ---------------------------------------------------------------------------
__global__ __launch_bounds__(256) void ta_norm_kernel(float* __restrict__ out)
{
    const int b = blockIdx.x;
    const int d = threadIdx.x;

    cudaGridDependencySynchronize();   // wait for ta_partial_kernel completion

    const float Linv = 1.0f / g_L[b];
    const float v = g_acc[b * DD + d];
    out[d * BB + b] = v * Linv;     // out is [D, B]
    g_acc[b * DD + d] = 0.f;        // reset for next graph replay
    if (d == 0) {
        __threadfence();            // order the L read above vs. reset below
        g_L[b] = 0.f;
    }
}

extern "C" void kernel_launch(void* const* d_in, const int* in_sizes, int n_in,
                              void* d_out, int out_size)
{
    const float* enc = (const float*)d_in[0];   // [B, S, D]
    const float* Ww  = (const float*)d_in[1];   // [1, D]
    // d_in[2] = We_b : scalar bias is softmax-invariant, dropped
    const float* ut  = (const float*)d_in[3];   // [1, 1]
    float* out = (float*)d_out;                 // [D, B]

    ta_partial_kernel<<<BB * NCC, 256>>>(enc, Ww, ut);

    cudaLaunchConfig_t cfg = {};
    cfg.gridDim  = dim3(BB, 1, 1);
    cfg.blockDim = dim3(256, 1, 1);
    cfg.dynamicSmemBytes = 0;
    cfg.stream = 0;
    cudaLaunchAttribute attr[1];
    attr[0].id = cudaLaunchAttributeProgrammaticStreamSerialization;
    attr[0].val.programmaticStreamSerializationAllowed = 1;
    cfg.attrs = attr;
    cfg.numAttrs = 1;
    cudaLaunchKernelEx(&cfg, ta_norm_kernel, out);
}